// round 5
// baseline (speedup 1.0000x reference)
#include <cuda_runtime.h>
#include <math.h>
#include <float.h>
#include <stdint.h>

#define NN 8192
#define DD 128
#define TOPK 30

typedef unsigned long long u64;

// ---- scratch (device globals; no runtime allocation allowed) ----
__device__ float g_M1t[DD * NN];              // M1^T  [128][8192]
__device__ float g_M2t[DD * NN];              // M2^T  [128][8192]

// ============================================================================
// packed f32x2 helpers (Blackwell sm_103a): 2 IEEE fp32 FMAs per issue slot.
// ============================================================================
__device__ __forceinline__ void fma2(u64& d, u64 a, u64 b) {
    asm("fma.rn.f32x2 %0, %1, %2, %0;" : "+l"(d) : "l"(a), "l"(b));
}
__device__ __forceinline__ u64 pack2(float x) {
    u64 r; asm("mov.b64 %0, {%1, %1};" : "=l"(r) : "f"(x)); return r;
}
__device__ __forceinline__ float2 unpk(u64 x) {
    float2 f; asm("mov.b64 {%0, %1}, %2;" : "=f"(f.x), "=f"(f.y) : "l"(x)); return f;
}

// ============================================================================
// XLA/Eigen f32 tanh replica (EmitTanh / generic_fast_tanh_float).
// ============================================================================
__device__ __forceinline__ float xla_tanh(float x) {
    const float kClamp = 7.90531110763549805f;
    const bool tiny = fabsf(x) < 0.0004f;
    float xc = fminf(fmaxf(x, -kClamp), kClamp);
    float x2 = xc * xc;
    float p = fmaf(x2, -2.76076847742355e-16f, 2.00018790482477e-13f);
    p = fmaf(x2, p, -8.60467152213735e-11f);
    p = fmaf(x2, p, 5.12229709037114e-08f);
    p = fmaf(x2, p, 1.48572235717979e-05f);
    p = fmaf(x2, p, 6.37261928875436e-04f);
    p = fmaf(x2, p, 4.89352455891786e-03f);
    p = xc * p;
    float q = fmaf(x2, 1.19825839466702e-06f, 1.18534705686654e-04f);
    q = fmaf(x2, q, 2.26843463243900e-03f);
    q = fmaf(x2, q, 4.89352518554385e-03f);
    float r = __fdiv_rn(p, q);
    return tiny ? x : r;
}

// ============================================================================
// Kernel 1: M = tanh(3*(E @ W^T + b)); transposed store, mode selects target.
// ============================================================================
__global__ void prep_kernel(const float* __restrict__ E,
                            const float* __restrict__ W,
                            const float* __restrict__ b,
                            int mode)
{
    extern __shared__ float sh[];
    float* Ws = sh;               // 128*128
    float* Es = sh + DD * DD;     // 32*128
    __shared__ float bs[DD];

    float* __restrict__ Mt = (mode == 0) ? g_M1t : g_M2t;

    const int tid = threadIdx.x;
    const int row0 = blockIdx.x * 32;

    {
        const float4* W4 = (const float4*)W;
        float4* Ws4 = (float4*)Ws;
        #pragma unroll 4
        for (int i = tid; i < DD * DD / 4; i += 256) Ws4[i] = W4[i];
        const float4* E4 = (const float4*)(E + (size_t)row0 * DD);
        float4* Es4 = (float4*)Es;
        #pragma unroll
        for (int i = tid; i < 32 * DD / 4; i += 256) Es4[i] = E4[i];
        if (tid < DD) bs[tid] = b[tid];
    }
    __syncthreads();

    const int tx = tid & 7;
    const int ty = tid >> 3;

    float acc[4][4];
    #pragma unroll
    for (int r = 0; r < 4; r++)
        #pragma unroll
        for (int c = 0; c < 4; c++) acc[r][c] = 0.0f;

    #pragma unroll 8
    for (int k = 0; k < DD; k += 4) {
        float4 ev[4], wv[4];
        #pragma unroll
        for (int r = 0; r < 4; r++) ev[r] = *(const float4*)&Es[(tx * 4 + r) * DD + k];
        #pragma unroll
        for (int c = 0; c < 4; c++) wv[c] = *(const float4*)&Ws[(ty * 4 + c) * DD + k];
        #pragma unroll
        for (int r = 0; r < 4; r++)
            #pragma unroll
            for (int c = 0; c < 4; c++) {
                acc[r][c] = fmaf(ev[r].x, wv[c].x, acc[r][c]);
                acc[r][c] = fmaf(ev[r].y, wv[c].y, acc[r][c]);
                acc[r][c] = fmaf(ev[r].z, wv[c].z, acc[r][c]);
                acc[r][c] = fmaf(ev[r].w, wv[c].w, acc[r][c]);
            }
    }

    #pragma unroll
    for (int r = 0; r < 4; r++) {
        const int row = row0 + tx * 4 + r;
        #pragma unroll
        for (int c = 0; c < 4; c++) {
            const int d = ty * 4 + c;
            const float t = acc[r][c] + bs[d];
            const float u = 3.0f * t;
            Mt[(size_t)d * NN + row] = xla_tanh(u);
        }
    }
}

// ============================================================================
// Kernel 2: P = M1@M2^T, Q = M2@M1^T via packed f32x2 FMA chains (ascending k,
// bit-exact per element). Upper-tri tiles only; A[j,i] = relu(Q-P) bitwise.
// Writes DIRECTLY into the output A region (aout).
// ============================================================================
#define BK 16
#define NCHUNK (DD / BK)

__device__ __forceinline__ void cp16(uint32_t smem_dst, const float* gsrc) {
    asm volatile("cp.async.ca.shared.global [%0], [%1], 16;\n"
                 :: "r"(smem_dst), "l"(gsrc));
}

__global__ void __launch_bounds__(256) gemm_kernel(float* __restrict__ aout)
{
    const int bi = blockIdx.y;
    const int bj = blockIdx.x;
    if (bj < bi) return;

    extern __shared__ float sh[];
    const int ARR = BK * 128;
    const int BUF = 4 * ARR;

    const int I0 = bi * 128, J0 = bj * 128;
    const int tid = threadIdx.x;
    const int tx = tid & 15;
    const int ty = tid >> 4;

    const uint32_t sbase = (uint32_t)__cvta_generic_to_shared(sh);

    int la[8], lk[8], lq[8];
    #pragma unroll
    for (int j = 0; j < 8; j++) {
        const int f = tid + 256 * j;
        la[j] = f >> 9;
        lk[j] = (f & 511) >> 5;
        lq[j] = f & 31;
    }

    auto issue_chunk = [&](int c, int buf) {
        const int kb = c * BK;
        #pragma unroll
        for (int j = 0; j < 8; j++) {
            const size_t gk = (size_t)(kb + lk[j]) * NN;
            const int col = ((la[j] & 1) ? J0 : I0) + lq[j] * 4;
            const float* src = ((la[j] & 2) ? g_M2t : g_M1t) + gk + col;
            cp16(sbase + (uint32_t)((buf * BUF + la[j] * ARR + lk[j] * 128 + lq[j] * 4) * 4), src);
        }
        asm volatile("cp.async.commit_group;\n");
    };

    issue_chunk(0, 0);

    u64 accP2[8][4], accQ2[8][4];
    #pragma unroll
    for (int r = 0; r < 8; r++)
        #pragma unroll
        for (int p = 0; p < 4; p++) { accP2[r][p] = 0ULL; accQ2[r][p] = 0ULL; }

    for (int c = 0; c < NCHUNK; c++) {
        const int cur = c & 1;
        if (c < NCHUNK - 1) {
            issue_chunk(c + 1, cur ^ 1);
            asm volatile("cp.async.wait_group 1;\n");
        } else {
            asm volatile("cp.async.wait_group 0;\n");
        }
        __syncthreads();

        const float* M1I = sh + cur * BUF + 0 * ARR;
        const float* M1J = sh + cur * BUF + 1 * ARR;
        const float* M2I = sh + cur * BUF + 2 * ARR;
        const float* M2J = sh + cur * BUF + 3 * ARR;

        #pragma unroll
        for (int kk = 0; kk < BK; kk++) {
            u64 a1d[8], a2d[8], b1p[4], b2p[4];
            {
                float4 t0 = *(const float4*)&M1I[kk * 128 + ty * 8];
                float4 t1 = *(const float4*)&M1I[kk * 128 + ty * 8 + 4];
                a1d[0]=pack2(t0.x); a1d[1]=pack2(t0.y); a1d[2]=pack2(t0.z); a1d[3]=pack2(t0.w);
                a1d[4]=pack2(t1.x); a1d[5]=pack2(t1.y); a1d[6]=pack2(t1.z); a1d[7]=pack2(t1.w);
                float4 u0 = *(const float4*)&M2I[kk * 128 + ty * 8];
                float4 u1 = *(const float4*)&M2I[kk * 128 + ty * 8 + 4];
                a2d[0]=pack2(u0.x); a2d[1]=pack2(u0.y); a2d[2]=pack2(u0.z); a2d[3]=pack2(u0.w);
                a2d[4]=pack2(u1.x); a2d[5]=pack2(u1.y); a2d[6]=pack2(u1.z); a2d[7]=pack2(u1.w);
                ulonglong2 q0 = *(const ulonglong2*)&M1J[kk * 128 + tx * 8];
                ulonglong2 q1 = *(const ulonglong2*)&M1J[kk * 128 + tx * 8 + 4];
                b1p[0]=q0.x; b1p[1]=q0.y; b1p[2]=q1.x; b1p[3]=q1.y;
                ulonglong2 w0 = *(const ulonglong2*)&M2J[kk * 128 + tx * 8];
                ulonglong2 w1 = *(const ulonglong2*)&M2J[kk * 128 + tx * 8 + 4];
                b2p[0]=w0.x; b2p[1]=w0.y; b2p[2]=w1.x; b2p[3]=w1.y;
            }
            #pragma unroll
            for (int r = 0; r < 8; r++)
                #pragma unroll
                for (int p = 0; p < 4; p++) {
                    fma2(accP2[r][p], a1d[r], b2p[p]);  // M1_i . M2_j
                    fma2(accQ2[r][p], a2d[r], b1p[p]);  // M2_i . M1_j
                }
        }
        __syncthreads();
    }

    float accP[8][8], accQ[8][8];
    #pragma unroll
    for (int r = 0; r < 8; r++)
        #pragma unroll
        for (int p = 0; p < 4; p++) {
            float2 fp = unpk(accP2[r][p]);
            float2 fq = unpk(accQ2[r][p]);
            accP[r][2*p] = fp.x; accP[r][2*p+1] = fp.y;
            accQ[r][2*p] = fq.x; accQ[r][2*p+1] = fq.y;
        }

    const int ibase = I0 + ty * 8;
    const int jbase = J0 + tx * 8;

    if (bi == bj) {
        #pragma unroll
        for (int r = 0; r < 8; r++) {
            const int ig = ibase + r;
            #pragma unroll
            for (int sg = 0; sg < 2; sg++) {
                float4 w;
                float* wp = &w.x;
                #pragma unroll
                for (int cc = 0; cc < 4; cc++) {
                    const int jg = jbase + sg * 4 + cc;
                    float x = fmaxf(accP[r][sg * 4 + cc] - accQ[r][sg * 4 + cc], 0.0f);
                    if (ig == jg) x = 0.0f;
                    wp[cc] = x;
                }
                *(float4*)&aout[(size_t)ig * NN + jbase + sg * 4] = w;
            }
        }
    } else {
        #pragma unroll
        for (int r = 0; r < 8; r++) {
            #pragma unroll
            for (int sg = 0; sg < 2; sg++) {
                float4 w;
                float* wp = &w.x;
                #pragma unroll
                for (int cc = 0; cc < 4; cc++)
                    wp[cc] = fmaxf(accP[r][sg * 4 + cc] - accQ[r][sg * 4 + cc], 0.0f);
                *(float4*)&aout[(size_t)(ibase + r) * NN + jbase + sg * 4] = w;
            }
        }
        #pragma unroll
        for (int s = 0; s < 8; s++) {
            const int jg = jbase + s;
            #pragma unroll
            for (int rg = 0; rg < 2; rg++) {
                float4 w;
                float* wp = &w.x;
                #pragma unroll
                for (int cc = 0; cc < 4; cc++)
                    wp[cc] = fmaxf(accQ[rg * 4 + cc][s] - accP[rg * 4 + cc][s], 0.0f);
                *(float4*)&aout[(size_t)jg * NN + ibase + rg * 4] = w;
            }
        }
    }
}

// ============================================================================
// Kernel 3: per-row top-30 via exact threshold pruning.
// Keys: (valbits<<13)|(8191-col): desc key == desc val, ties lower col first.
// Per warp: T = 30th largest of {per-lane top-2} (provable lower bound on true
// 30th); keep keys >= T (>=30 guaranteed); if <=64 candidates, one warp
// bitonic sort of 64 gives the warp's top-30. Else: fall back to full
// per-thread sort + 30-pop merge (always correct). Reads A from the output
// region, zeroes it, scatters winners.
// dyn smem = 65536 B.
// ============================================================================
__device__ __forceinline__ u64 shfl64_xor(u64 x, int off) {
    return __shfl_xor_sync(0xffffffffu, x, off);
}

// warp-collective bitonic sort (descending) of 64 u64 keys, 2 per lane.
// virtual index v = 2*lane + r.
__device__ __forceinline__ void warp_sort64_desc(u64& e0, u64& e1, int lane) {
    #pragma unroll
    for (int size = 2; size <= 64; size <<= 1) {
        #pragma unroll
        for (int stride = size >> 1; stride > 0; stride >>= 1) {
            const bool desc = (((2 * lane) & size) == 0);
            if (stride == 1) {
                const u64 lo = (e0 < e1) ? e0 : e1;
                const u64 hi = (e0 < e1) ? e1 : e0;
                e0 = desc ? hi : lo;
                e1 = desc ? lo : hi;
            } else {
                const int half = stride >> 1;
                const u64 p0 = shfl64_xor(e0, half);
                const u64 p1 = shfl64_xor(e1, half);
                const bool first = (((2 * lane) & stride) == 0);
                const bool keepmax = (first == desc);
                e0 = keepmax ? (e0 > p0 ? e0 : p0) : (e0 < p0 ? e0 : p0);
                e1 = keepmax ? (e1 > p1 ? e1 : p1) : (e1 < p1 ? e1 : p1);
            }
        }
    }
}

__global__ void __launch_bounds__(256) topk_kernel(float* __restrict__ out,
                                                   long long abase,
                                                   int write_edges)
{
    extern __shared__ u64 shbuf[];            // 8 warps x 1024 u64 (8KB each)
    __shared__ u64 wtop[8][TOPK];
    __shared__ u64 topkeys[TOPK];

    const int row = blockIdx.x;
    const int tid = threadIdx.x;
    const int lane = tid & 31;
    const int w = tid >> 5;
    float* arow = out + abase + (size_t)row * NN;

    // load 32 values from output A region, zero it, pack keys
    u64 k[32];
    const float4 z4 = make_float4(0.f, 0.f, 0.f, 0.f);
    #pragma unroll
    for (int q = 0; q < 8; q++) {
        const int base = (tid + 256 * q) * 4;
        float4 t = *(const float4*)&arow[base];
        *(float4*)&arow[base] = z4;
        k[q*4+0] = ((u64)__float_as_uint(t.x) << 13) | (u64)(8191 - (base + 0));
        k[q*4+1] = ((u64)__float_as_uint(t.y) << 13) | (u64)(8191 - (base + 1));
        k[q*4+2] = ((u64)__float_as_uint(t.z) << 13) | (u64)(8191 - (base + 2));
        k[q*4+3] = ((u64)__float_as_uint(t.w) << 13) | (u64)(8191 - (base + 3));
    }

    u64* wbuf = shbuf + w * 1024;   // this warp's scratch region

    // ---- phase 1: per-lane top-2, warp-sort 64, T = 30th largest ----
    u64 m1 = (k[0] > k[1]) ? k[0] : k[1];
    u64 m2 = (k[0] > k[1]) ? k[1] : k[0];
    #pragma unroll
    for (int i = 2; i < 32; i++) {
        const u64 v = k[i];
        const bool g1 = v > m1;
        const u64 nm2 = g1 ? m1 : ((v > m2) ? v : m2);
        m1 = g1 ? v : m1;
        m2 = nm2;
    }
    warp_sort64_desc(m1, m2, lane);
    const u64 T = shfl64_xor((lane == 14) ? m2 : 0ULL, lane ^ 14) ;  // broadcast item 29
    // simpler correct broadcast:
    const u64 Tb = __shfl_sync(0xffffffffu, m2, 14);
    const u64 thr = Tb;
    (void)T;

    // ---- phase 2: count + compact candidates >= thr ----
    wbuf[2 * lane] = 0ULL;
    wbuf[2 * lane + 1] = 0ULL;
    __syncwarp();
    const unsigned lml = (1u << lane) - 1u;
    int cnt = 0;
    #pragma unroll
    for (int i = 0; i < 32; i++) {
        const bool p = (k[i] >= thr);
        const unsigned m = __ballot_sync(0xffffffffu, p);
        if (p) {
            const int pos = cnt + __popc(m & lml);
            if (pos < 64) wbuf[pos] = k[i];
        }
        cnt += __popc(m);
    }
    __syncwarp();

    if (cnt <= 64) {
        // ---- fast path: sort 64 candidates, winners = first 30 ----
        u64 c0 = wbuf[2 * lane];
        u64 c1 = wbuf[2 * lane + 1];
        warp_sort64_desc(c0, c1, lane);
        if (2 * lane < TOPK) {
            wtop[w][2 * lane] = c0;
            if (2 * lane + 1 < TOPK) wtop[w][2 * lane + 1] = c1;
        }
    } else {
        // ---- fallback: full per-thread bitonic sort + 30-pop merge ----
        #pragma unroll
        for (int size = 2; size <= 32; size <<= 1) {
            #pragma unroll
            for (int stride = size >> 1; stride > 0; stride >>= 1) {
                #pragma unroll
                for (int i = 0; i < 32; i++) {
                    const int j = i ^ stride;
                    if (j > i) {
                        const bool desc = ((i & size) == 0);
                        const u64 lo = (k[i] < k[j]) ? k[i] : k[j];
                        const u64 hi = (k[i] < k[j]) ? k[j] : k[i];
                        k[i] = desc ? hi : lo;
                        k[j] = desc ? lo : hi;
                    }
                }
            }
        }
        u64* mylist = wbuf + lane * 32;
        #pragma unroll
        for (int i = 0; i < 32; i++) mylist[i] = k[i];
        __syncwarp();
        int h = 0;
        u64 head = k[0];
        for (int it = 0; it < TOPK; it++) {
            u64 m = head;
            #pragma unroll
            for (int off = 16; off; off >>= 1) {
                const u64 om = shfl64_xor(m, off);
                if (om > m) m = om;
            }
            if (lane == 0) wtop[w][it] = m;
            if (head == m) { h++; head = mylist[h]; }
        }
    }
    __syncthreads();

    // ---- final merge: warp 0, lanes 0..7 hold sorted list heads ----
    if (w == 0) {
        int h = 0;
        u64 head = (lane < 8) ? wtop[lane][0] : 0ULL;
        for (int it = 0; it < TOPK; it++) {
            u64 m = head;
            #pragma unroll
            for (int off = 4; off; off >>= 1) {
                const u64 om = shfl64_xor(m, off);
                if (om > m) m = om;
            }
            if (lane == 0) topkeys[it] = m;
            if (lane < 8 && head == m) {
                h++;
                head = (h < TOPK) ? wtop[lane][h] : 0ULL;
            }
        }
    }
    __syncthreads();

    if (tid < TOPK) {
        const u64 key = topkeys[tid];
        const float val = __uint_as_float((unsigned)(key >> 13));
        const int dst = 8191 - (int)(key & 8191);
        arow[dst] = val;
        if (write_edges) {
            const long long e = (long long)row * TOPK + tid;
            out[e] = (float)row;                                // src
            out[(long long)NN * TOPK + e] = (float)dst;         // dst
            out[2LL * NN * TOPK + e] = val;                     // attr
        }
    }
}

// ============================================================================
// launch
// ============================================================================
extern "C" void kernel_launch(void* const* d_in, const int* in_sizes, int n_in,
                              void* d_out, int out_size)
{
    const float* E1 = (const float*)d_in[0];
    const float* E2 = (const float*)d_in[1];
    const float* W1 = (const float*)d_in[2];
    const float* b1 = (const float*)d_in[3];
    const float* W2 = (const float*)d_in[4];
    const float* b2 = (const float*)d_in[5];
    float* out = (float*)d_out;

    cudaFuncSetAttribute(prep_kernel, cudaFuncAttributeMaxDynamicSharedMemorySize, 81920);
    cudaFuncSetAttribute(gemm_kernel, cudaFuncAttributeMaxDynamicSharedMemorySize, 65536);
    cudaFuncSetAttribute(topk_kernel, cudaFuncAttributeMaxDynamicSharedMemorySize, 65536);

    long long abase;
    int write_edges;
    if (out_size == (long long)NN * NN) { abase = 0; write_edges = 0; }
    else { abase = 3LL * NN * TOPK; write_edges = 1; }

    prep_kernel<<<NN / 32, 256, 81920>>>(E1, W1, b1, 0);
    prep_kernel<<<NN / 32, 256, 81920>>>(E2, W2, b2, 1);
    gemm_kernel<<<dim3(64, 64), 256, 65536>>>(out + abase);
    topk_kernel<<<NN, 256, 65536>>>(out, abase, write_edges);
}

// round 6
// speedup vs baseline: 1.2194x; 1.2194x over previous
#include <cuda_runtime.h>
#include <math.h>
#include <float.h>
#include <stdint.h>

#define NN 8192
#define DD 128
#define TOPK 30

typedef unsigned long long u64;

// ---- scratch (device globals; no runtime allocation allowed) ----
__device__ float g_M1t[DD * NN];              // M1^T  [128][8192]
__device__ float g_M2t[DD * NN];              // M2^T  [128][8192]

// ============================================================================
// packed f32x2 helpers (Blackwell sm_103a): 2 IEEE fp32 FMAs per issue slot.
// ============================================================================
__device__ __forceinline__ void fma2(u64& d, u64 a, u64 b) {
    asm("fma.rn.f32x2 %0, %1, %2, %0;" : "+l"(d) : "l"(a), "l"(b));
}
__device__ __forceinline__ u64 pack2(float x) {
    u64 r; asm("mov.b64 %0, {%1, %1};" : "=l"(r) : "f"(x)); return r;
}
__device__ __forceinline__ float2 unpk(u64 x) {
    float2 f; asm("mov.b64 {%0, %1}, %2;" : "=f"(f.x), "=f"(f.y) : "l"(x)); return f;
}

// ============================================================================
// XLA/Eigen f32 tanh replica (EmitTanh / generic_fast_tanh_float).
// ============================================================================
__device__ __forceinline__ float xla_tanh(float x) {
    const float kClamp = 7.90531110763549805f;
    const bool tiny = fabsf(x) < 0.0004f;
    float xc = fminf(fmaxf(x, -kClamp), kClamp);
    float x2 = xc * xc;
    float p = fmaf(x2, -2.76076847742355e-16f, 2.00018790482477e-13f);
    p = fmaf(x2, p, -8.60467152213735e-11f);
    p = fmaf(x2, p, 5.12229709037114e-08f);
    p = fmaf(x2, p, 1.48572235717979e-05f);
    p = fmaf(x2, p, 6.37261928875436e-04f);
    p = fmaf(x2, p, 4.89352455891786e-03f);
    p = xc * p;
    float q = fmaf(x2, 1.19825839466702e-06f, 1.18534705686654e-04f);
    q = fmaf(x2, q, 2.26843463243900e-03f);
    q = fmaf(x2, q, 4.89352518554385e-03f);
    float r = __fdiv_rn(p, q);
    return tiny ? x : r;
}

// ============================================================================
// Kernel 1 (fused): M = tanh(3*(E @ W^T + b)); transposed store.
// blockIdx.y = mode (0: E1/W1/b1 -> g_M1t, 1: E2/W2/b2 -> g_M2t).
// ============================================================================
__global__ void prep_kernel(const float* __restrict__ E1,
                            const float* __restrict__ W1,
                            const float* __restrict__ b1,
                            const float* __restrict__ E2,
                            const float* __restrict__ W2,
                            const float* __restrict__ b2)
{
    extern __shared__ float sh[];
    float* Ws = sh;               // 128*128
    float* Es = sh + DD * DD;     // 32*128
    __shared__ float bs[DD];

    const int mode = blockIdx.y;
    const float* __restrict__ E = mode ? E2 : E1;
    const float* __restrict__ W = mode ? W2 : W1;
    const float* __restrict__ b = mode ? b2 : b1;
    float* __restrict__ Mt = mode ? g_M2t : g_M1t;

    const int tid = threadIdx.x;
    const int row0 = blockIdx.x * 32;

    {
        const float4* W4 = (const float4*)W;
        float4* Ws4 = (float4*)Ws;
        #pragma unroll 4
        for (int i = tid; i < DD * DD / 4; i += 256) Ws4[i] = W4[i];
        const float4* E4 = (const float4*)(E + (size_t)row0 * DD);
        float4* Es4 = (float4*)Es;
        #pragma unroll
        for (int i = tid; i < 32 * DD / 4; i += 256) Es4[i] = E4[i];
        if (tid < DD) bs[tid] = b[tid];
    }
    __syncthreads();

    const int tx = tid & 7;
    const int ty = tid >> 3;

    float acc[4][4];
    #pragma unroll
    for (int r = 0; r < 4; r++)
        #pragma unroll
        for (int c = 0; c < 4; c++) acc[r][c] = 0.0f;

    #pragma unroll 8
    for (int k = 0; k < DD; k += 4) {
        float4 ev[4], wv[4];
        #pragma unroll
        for (int r = 0; r < 4; r++) ev[r] = *(const float4*)&Es[(tx * 4 + r) * DD + k];
        #pragma unroll
        for (int c = 0; c < 4; c++) wv[c] = *(const float4*)&Ws[(ty * 4 + c) * DD + k];
        #pragma unroll
        for (int r = 0; r < 4; r++)
            #pragma unroll
            for (int c = 0; c < 4; c++) {
                acc[r][c] = fmaf(ev[r].x, wv[c].x, acc[r][c]);
                acc[r][c] = fmaf(ev[r].y, wv[c].y, acc[r][c]);
                acc[r][c] = fmaf(ev[r].z, wv[c].z, acc[r][c]);
                acc[r][c] = fmaf(ev[r].w, wv[c].w, acc[r][c]);
            }
    }

    #pragma unroll
    for (int r = 0; r < 4; r++) {
        const int row = row0 + tx * 4 + r;
        #pragma unroll
        for (int c = 0; c < 4; c++) {
            const int d = ty * 4 + c;
            const float t = acc[r][c] + bs[d];
            const float u = 3.0f * t;
            Mt[(size_t)d * NN + row] = xla_tanh(u);
        }
    }
}

// ============================================================================
// Kernel 2: 128x64 tile, 256 threads, 2 CTAs/SM. P = M1@M2^T, Q = M2@M1^T via
// row-paired f32x2 FMA chains (ascending k, bit-exact per element).
// Tiles kept iff bj >= 2*bi; A[i,j]=relu(P-Q), mirror A[j,i]=relu(Q-P).
// Diagonal-crossing tiles (bj>>1 == bi) use scalar predicated stores.
// dyn smem = 49152 B.
// ============================================================================
#define BK 16
#define NCHUNK (DD / BK)
#define ARR_I (BK * 128)          // 2048 floats per I-side array
#define ARR_J (BK * 64)           // 1024 floats per J-side array
#define BUF (2 * ARR_I + 2 * ARR_J)   // 6144 floats per buffer

__device__ __forceinline__ void cp16(uint32_t smem_dst, const float* gsrc) {
    asm volatile("cp.async.ca.shared.global [%0], [%1], 16;\n"
                 :: "r"(smem_dst), "l"(gsrc));
}

__global__ void __launch_bounds__(256, 2) gemm_kernel(float* __restrict__ aout)
{
    const int bi = blockIdx.y;       // 0..63, rows I0..I0+127
    const int bj = blockIdx.x;       // 0..127, cols J0..J0+63
    if (bj < 2 * bi) return;

    extern __shared__ float sh[];

    const int I0 = bi * 128, J0 = bj * 64;
    const int tid = threadIdx.x;
    const int tx = tid & 15;         // 16 col groups of 4
    const int ty = tid >> 4;         // 16 row groups of 8

    const uint32_t sbase = (uint32_t)__cvta_generic_to_shared(sh);

    auto issue_chunk = [&](int c, int buf) {
        const int kb = c * BK;
        // I-side: M1I (arr 0), M2I (arr 1): 1024 float4 over 4 iters
        #pragma unroll
        for (int j = 0; j < 4; j++) {
            const int f = tid + 256 * j;        // 0..1023
            const int arr = f >> 9;             // 0: M1I, 1: M2I
            const int idx = f & 511;
            const int kk = idx >> 5, q = idx & 31;
            const float* src = (arr ? g_M2t : g_M1t) + (size_t)(kb + kk) * NN + I0 + q * 4;
            cp16(sbase + (uint32_t)((buf * BUF + arr * ARR_I + kk * 128 + q * 4) * 4), src);
        }
        // J-side: M1J, M2J: 256 float4 each
        {
            const int kk = tid >> 4, q = tid & 15;
            const size_t gk = (size_t)(kb + kk) * NN + J0 + q * 4;
            cp16(sbase + (uint32_t)((buf * BUF + 2 * ARR_I + kk * 64 + q * 4) * 4), g_M1t + gk);
            cp16(sbase + (uint32_t)((buf * BUF + 2 * ARR_I + ARR_J + kk * 64 + q * 4) * 4), g_M2t + gk);
        }
        asm volatile("cp.async.commit_group;\n");
    };

    issue_chunk(0, 0);

    // accP[rp][c]: lanes = (row ty*8+2rp, ty*8+2rp+1), col jbase+c
    u64 accP[4][4], accQ[4][4];
    #pragma unroll
    for (int r = 0; r < 4; r++)
        #pragma unroll
        for (int c = 0; c < 4; c++) { accP[r][c] = 0ULL; accQ[r][c] = 0ULL; }

    for (int c = 0; c < NCHUNK; c++) {
        const int cur = c & 1;
        if (c < NCHUNK - 1) {
            issue_chunk(c + 1, cur ^ 1);
            asm volatile("cp.async.wait_group 1;\n");
        } else {
            asm volatile("cp.async.wait_group 0;\n");
        }
        __syncthreads();

        const float* M1I = sh + cur * BUF;
        const float* M2I = sh + cur * BUF + ARR_I;
        const float* M1J = sh + cur * BUF + 2 * ARR_I;
        const float* M2J = sh + cur * BUF + 2 * ARR_I + ARR_J;

        #pragma unroll
        for (int kk = 0; kk < BK; kk++) {
            // a-side: row pairs load directly as u64 (rows contiguous)
            ulonglong2 a1lo = *(const ulonglong2*)&M1I[kk * 128 + ty * 8];
            ulonglong2 a1hi = *(const ulonglong2*)&M1I[kk * 128 + ty * 8 + 4];
            ulonglong2 a2lo = *(const ulonglong2*)&M2I[kk * 128 + ty * 8];
            ulonglong2 a2hi = *(const ulonglong2*)&M2I[kk * 128 + ty * 8 + 4];
            u64 a1p[4] = { a1lo.x, a1lo.y, a1hi.x, a1hi.y };
            u64 a2p[4] = { a2lo.x, a2lo.y, a2hi.x, a2hi.y };
            // b-side: 4 cols per matrix, duplicated
            float4 f1 = *(const float4*)&M1J[kk * 64 + tx * 4];
            float4 f2 = *(const float4*)&M2J[kk * 64 + tx * 4];
            u64 b1d[4] = { pack2(f1.x), pack2(f1.y), pack2(f1.z), pack2(f1.w) };
            u64 b2d[4] = { pack2(f2.x), pack2(f2.y), pack2(f2.z), pack2(f2.w) };
            #pragma unroll
            for (int rp = 0; rp < 4; rp++)
                #pragma unroll
                for (int cc = 0; cc < 4; cc++) {
                    fma2(accP[rp][cc], a1p[rp], b2d[cc]);  // M1_i . M2_j
                    fma2(accQ[rp][cc], a2p[rp], b1d[cc]);  // M2_i . M1_j
                }
        }
        __syncthreads();
    }

    // unpack
    float P[8][4], Q[8][4];
    #pragma unroll
    for (int rp = 0; rp < 4; rp++)
        #pragma unroll
        for (int cc = 0; cc < 4; cc++) {
            float2 fp = unpk(accP[rp][cc]);
            float2 fq = unpk(accQ[rp][cc]);
            P[2*rp][cc] = fp.x; P[2*rp+1][cc] = fp.y;
            Q[2*rp][cc] = fq.x; Q[2*rp+1][cc] = fq.y;
        }

    const int ibase = I0 + ty * 8;
    const int jbase = J0 + tx * 4;
    const bool cross = ((bj >> 1) == bi);   // tile intersects the diagonal

    if (!cross) {
        // all j > i: full float4 stores
        #pragma unroll
        for (int r = 0; r < 8; r++) {
            float4 w;
            w.x = fmaxf(P[r][0] - Q[r][0], 0.0f);
            w.y = fmaxf(P[r][1] - Q[r][1], 0.0f);
            w.z = fmaxf(P[r][2] - Q[r][2], 0.0f);
            w.w = fmaxf(P[r][3] - Q[r][3], 0.0f);
            *(float4*)&aout[(size_t)(ibase + r) * NN + jbase] = w;
        }
        #pragma unroll
        for (int cc = 0; cc < 4; cc++) {
            const int jg = jbase + cc;
            float4 w0, w1;
            w0.x = fmaxf(Q[0][cc] - P[0][cc], 0.0f);
            w0.y = fmaxf(Q[1][cc] - P[1][cc], 0.0f);
            w0.z = fmaxf(Q[2][cc] - P[2][cc], 0.0f);
            w0.w = fmaxf(Q[3][cc] - P[3][cc], 0.0f);
            w1.x = fmaxf(Q[4][cc] - P[4][cc], 0.0f);
            w1.y = fmaxf(Q[5][cc] - P[5][cc], 0.0f);
            w1.z = fmaxf(Q[6][cc] - P[6][cc], 0.0f);
            w1.w = fmaxf(Q[7][cc] - P[7][cc], 0.0f);
            *(float4*)&aout[(size_t)jg * NN + ibase] = w0;
            *(float4*)&aout[(size_t)jg * NN + ibase + 4] = w1;
        }
    } else {
        // diagonal-crossing tile: scalar predicated stores
        #pragma unroll
        for (int r = 0; r < 8; r++) {
            const int ig = ibase + r;
            #pragma unroll
            for (int cc = 0; cc < 4; cc++) {
                const int jg = jbase + cc;
                if (jg > ig) {
                    aout[(size_t)ig * NN + jg] = fmaxf(P[r][cc] - Q[r][cc], 0.0f);
                    aout[(size_t)jg * NN + ig] = fmaxf(Q[r][cc] - P[r][cc], 0.0f);
                } else if (jg == ig) {
                    aout[(size_t)ig * NN + jg] = 0.0f;
                }
            }
        }
    }
}

// ============================================================================
// Kernel 3: per-row top-30 via per-thread bitonic sort + per-warp sorted-list
// merge + final 8-way merge (round-4 version, known good).
// Keys: (valbits<<13)|(8191-col). dyn smem = 65536 B.
// ============================================================================
__device__ __forceinline__ u64 shfl64_xor(u64 x, int off) {
    unsigned lo = (unsigned)x, hi = (unsigned)(x >> 32);
    lo = __shfl_xor_sync(0xffffffffu, lo, off);
    hi = __shfl_xor_sync(0xffffffffu, hi, off);
    return ((u64)hi << 32) | lo;
}

__global__ void __launch_bounds__(256) topk_kernel(float* __restrict__ out,
                                                   long long abase,
                                                   int write_edges)
{
    extern __shared__ u64 lists[];            // [256][32]
    __shared__ u64 wtop[8][TOPK];
    __shared__ u64 topkeys[TOPK];

    const int row = blockIdx.x;
    const int tid = threadIdx.x;
    const int lane = tid & 31;
    const int w = tid >> 5;
    float* arow = out + abase + (size_t)row * NN;

    u64 k[32];
    const float4 z4 = make_float4(0.f, 0.f, 0.f, 0.f);
    #pragma unroll
    for (int q = 0; q < 8; q++) {
        const int base = (tid + 256 * q) * 4;
        float4 t = *(const float4*)&arow[base];
        *(float4*)&arow[base] = z4;
        k[q*4+0] = ((u64)__float_as_uint(t.x) << 13) | (u64)(8191 - (base + 0));
        k[q*4+1] = ((u64)__float_as_uint(t.y) << 13) | (u64)(8191 - (base + 1));
        k[q*4+2] = ((u64)__float_as_uint(t.z) << 13) | (u64)(8191 - (base + 2));
        k[q*4+3] = ((u64)__float_as_uint(t.w) << 13) | (u64)(8191 - (base + 3));
    }

    // per-thread bitonic sort, descending
    #pragma unroll
    for (int size = 2; size <= 32; size <<= 1) {
        #pragma unroll
        for (int stride = size >> 1; stride > 0; stride >>= 1) {
            #pragma unroll
            for (int i = 0; i < 32; i++) {
                const int j = i ^ stride;
                if (j > i) {
                    const bool desc = ((i & size) == 0);
                    const u64 lo = (k[i] < k[j]) ? k[i] : k[j];
                    const u64 hi = (k[i] < k[j]) ? k[j] : k[i];
                    k[i] = desc ? hi : lo;
                    k[j] = desc ? lo : hi;
                }
            }
        }
    }

    u64* mylist = lists + tid * 32;
    #pragma unroll
    for (int i = 0; i < 32; i++) mylist[i] = k[i];

    // per-warp merge: 30 pops over 32 sorted lists
    {
        int h = 0;
        u64 head = k[0];
        for (int it = 0; it < TOPK; it++) {
            u64 m = head;
            #pragma unroll
            for (int off = 16; off; off >>= 1) {
                u64 om = shfl64_xor(m, off);
                if (om > m) m = om;
            }
            if (lane == 0) wtop[w][it] = m;
            if (head == m) { h++; head = mylist[h]; }
        }
    }
    __syncthreads();

    // final merge: warp 0, lanes 0..7 hold list heads
    if (w == 0) {
        int h = 0;
        u64 head = (lane < 8) ? wtop[lane][0] : 0ULL;
        for (int it = 0; it < TOPK; it++) {
            u64 m = head;
            #pragma unroll
            for (int off = 4; off; off >>= 1) {
                u64 om = shfl64_xor(m, off);
                if (om > m) m = om;
            }
            if (lane == 0) topkeys[it] = m;
            if (lane < 8 && head == m) {
                h++;
                head = (h < TOPK) ? wtop[lane][h] : 0ULL;
            }
        }
    }
    __syncthreads();

    if (tid < TOPK) {
        const u64 key = topkeys[tid];
        const float val = __uint_as_float((unsigned)(key >> 13));
        const int dst = 8191 - (int)(key & 8191);
        arow[dst] = val;
        if (write_edges) {
            const long long e = (long long)row * TOPK + tid;
            out[e] = (float)row;                                // src
            out[(long long)NN * TOPK + e] = (float)dst;         // dst
            out[2LL * NN * TOPK + e] = val;                     // attr
        }
    }
}

// ============================================================================
// launch
// ============================================================================
extern "C" void kernel_launch(void* const* d_in, const int* in_sizes, int n_in,
                              void* d_out, int out_size)
{
    const float* E1 = (const float*)d_in[0];
    const float* E2 = (const float*)d_in[1];
    const float* W1 = (const float*)d_in[2];
    const float* b1 = (const float*)d_in[3];
    const float* W2 = (const float*)d_in[4];
    const float* b2 = (const float*)d_in[5];
    float* out = (float*)d_out;

    cudaFuncSetAttribute(prep_kernel, cudaFuncAttributeMaxDynamicSharedMemorySize, 81920);
    cudaFuncSetAttribute(gemm_kernel, cudaFuncAttributeMaxDynamicSharedMemorySize, 49152);
    cudaFuncSetAttribute(topk_kernel, cudaFuncAttributeMaxDynamicSharedMemorySize, 65536);

    long long abase;
    int write_edges;
    if (out_size == (long long)NN * NN) { abase = 0; write_edges = 0; }
    else { abase = 3LL * NN * TOPK; write_edges = 1; }

    prep_kernel<<<dim3(NN / 32, 2), 256, 81920>>>(E1, W1, b1, E2, W2, b2);
    gemm_kernel<<<dim3(128, 64), 256, 49152>>>(out + abase);
    topk_kernel<<<NN, 256, 65536>>>(out, abase, write_edges);
}

// round 7
// speedup vs baseline: 1.6548x; 1.3570x over previous
#include <cuda_runtime.h>
#include <math.h>
#include <float.h>
#include <stdint.h>

#define NN 8192
#define DD 128
#define TOPK 30

typedef unsigned long long u64;

// ---- scratch (device globals; no runtime allocation allowed) ----
__device__ float g_M1t[DD * NN];              // M1^T  [128][8192]
__device__ float g_M2t[DD * NN];              // M2^T  [128][8192]

// ============================================================================
// packed f32x2 helpers (Blackwell sm_103a): 2 IEEE fp32 FMAs per issue slot.
// ============================================================================
__device__ __forceinline__ void fma2(u64& d, u64 a, u64 b) {
    asm("fma.rn.f32x2 %0, %1, %2, %0;" : "+l"(d) : "l"(a), "l"(b));
}
__device__ __forceinline__ u64 pack2(float x) {
    u64 r; asm("mov.b64 %0, {%1, %1};" : "=l"(r) : "f"(x)); return r;
}
__device__ __forceinline__ float2 unpk(u64 x) {
    float2 f; asm("mov.b64 {%0, %1}, %2;" : "=f"(f.x), "=f"(f.y) : "l"(x)); return f;
}

// ============================================================================
// XLA/Eigen f32 tanh replica (EmitTanh / generic_fast_tanh_float).
// ============================================================================
__device__ __forceinline__ float xla_tanh(float x) {
    const float kClamp = 7.90531110763549805f;
    const bool tiny = fabsf(x) < 0.0004f;
    float xc = fminf(fmaxf(x, -kClamp), kClamp);
    float x2 = xc * xc;
    float p = fmaf(x2, -2.76076847742355e-16f, 2.00018790482477e-13f);
    p = fmaf(x2, p, -8.60467152213735e-11f);
    p = fmaf(x2, p, 5.12229709037114e-08f);
    p = fmaf(x2, p, 1.48572235717979e-05f);
    p = fmaf(x2, p, 6.37261928875436e-04f);
    p = fmaf(x2, p, 4.89352455891786e-03f);
    p = xc * p;
    float q = fmaf(x2, 1.19825839466702e-06f, 1.18534705686654e-04f);
    q = fmaf(x2, q, 2.26843463243900e-03f);
    q = fmaf(x2, q, 4.89352518554385e-03f);
    float r = __fdiv_rn(p, q);
    return tiny ? x : r;
}

// ============================================================================
// Kernel 1 (fused): M = tanh(3*(E @ W^T + b)); transposed store.
// Row-rotation swizzle: row m stored rotated by 4*(m>>2) columns -> readers
// hit 32 distinct banks (Es) / 4 distinct bank-quads (Ws): conflict-free.
// blockIdx.y = mode (0 -> g_M1t, 1 -> g_M2t).
// ============================================================================
__global__ void prep_kernel(const float* __restrict__ E1,
                            const float* __restrict__ W1,
                            const float* __restrict__ b1,
                            const float* __restrict__ E2,
                            const float* __restrict__ W2,
                            const float* __restrict__ b2)
{
    extern __shared__ float sh[];
    float* Ws = sh;               // 128 rows x 128 (swizzled)
    float* Es = sh + DD * DD;     // 32 rows x 128 (swizzled)
    __shared__ float bs[DD];

    const int mode = blockIdx.y;
    const float* __restrict__ E = mode ? E2 : E1;
    const float* __restrict__ W = mode ? W2 : W1;
    const float* __restrict__ b = mode ? b2 : b1;
    float* __restrict__ Mt = mode ? g_M2t : g_M1t;

    const int tid = threadIdx.x;
    const int row0 = blockIdx.x * 32;

    {
        const float4* W4 = (const float4*)W;
        #pragma unroll 4
        for (int i = tid; i < DD * DD / 4; i += 256) {
            const int rowm = i >> 5, q = i & 31;
            float4 v = W4[i];
            *(float4*)&Ws[rowm * DD + ((4 * q + 4 * (rowm >> 2)) & 127)] = v;
        }
        const float4* E4 = (const float4*)(E + (size_t)row0 * DD);
        #pragma unroll
        for (int i = tid; i < 32 * DD / 4; i += 256) {
            const int rowm = i >> 5, q = i & 31;
            float4 v = E4[i];
            *(float4*)&Es[rowm * DD + ((4 * q + 4 * (rowm >> 2)) & 127)] = v;
        }
        if (tid < DD) bs[tid] = b[tid];
    }
    __syncthreads();

    const int tx = tid & 7;    // row group (4 rows)
    const int ty = tid >> 3;   // d group (4 cols)

    float acc[4][4];
    #pragma unroll
    for (int r = 0; r < 4; r++)
        #pragma unroll
        for (int c = 0; c < 4; c++) acc[r][c] = 0.0f;

    #pragma unroll 8
    for (int k = 0; k < DD; k += 4) {
        const int ke = (k + 4 * tx) & 127;   // rotated column for rows 4tx..4tx+3
        const int kw = (k + 4 * ty) & 127;   // rotated column for rows 4ty..4ty+3
        float4 ev[4], wv[4];
        #pragma unroll
        for (int r = 0; r < 4; r++) ev[r] = *(const float4*)&Es[(tx * 4 + r) * DD + ke];
        #pragma unroll
        for (int c = 0; c < 4; c++) wv[c] = *(const float4*)&Ws[(ty * 4 + c) * DD + kw];
        #pragma unroll
        for (int r = 0; r < 4; r++)
            #pragma unroll
            for (int c = 0; c < 4; c++) {
                acc[r][c] = fmaf(ev[r].x, wv[c].x, acc[r][c]);
                acc[r][c] = fmaf(ev[r].y, wv[c].y, acc[r][c]);
                acc[r][c] = fmaf(ev[r].z, wv[c].z, acc[r][c]);
                acc[r][c] = fmaf(ev[r].w, wv[c].w, acc[r][c]);
            }
    }

    #pragma unroll
    for (int r = 0; r < 4; r++) {
        const int row = row0 + tx * 4 + r;
        #pragma unroll
        for (int c = 0; c < 4; c++) {
            const int d = ty * 4 + c;
            const float t = acc[r][c] + bs[d];
            const float u = 3.0f * t;
            Mt[(size_t)d * NN + row] = xla_tanh(u);
        }
    }
}

// ============================================================================
// Kernel 2: 128x64 tile, 2 CTAs/SM, row-paired f32x2 FMA chains (unchanged
// from round 6; bit-exact ascending-k per element). bj >= 2*bi tiles only.
// ============================================================================
#define BK 16
#define NCHUNK (DD / BK)
#define ARR_I (BK * 128)
#define ARR_J (BK * 64)
#define BUF (2 * ARR_I + 2 * ARR_J)

__device__ __forceinline__ void cp16(uint32_t smem_dst, const float* gsrc) {
    asm volatile("cp.async.ca.shared.global [%0], [%1], 16;\n"
                 :: "r"(smem_dst), "l"(gsrc));
}

__global__ void __launch_bounds__(256, 2) gemm_kernel(float* __restrict__ aout)
{
    const int bi = blockIdx.y;
    const int bj = blockIdx.x;
    if (bj < 2 * bi) return;

    extern __shared__ float sh[];

    const int I0 = bi * 128, J0 = bj * 64;
    const int tid = threadIdx.x;
    const int tx = tid & 15;
    const int ty = tid >> 4;

    const uint32_t sbase = (uint32_t)__cvta_generic_to_shared(sh);

    auto issue_chunk = [&](int c, int buf) {
        const int kb = c * BK;
        #pragma unroll
        for (int j = 0; j < 4; j++) {
            const int f = tid + 256 * j;
            const int arr = f >> 9;
            const int idx = f & 511;
            const int kk = idx >> 5, q = idx & 31;
            const float* src = (arr ? g_M2t : g_M1t) + (size_t)(kb + kk) * NN + I0 + q * 4;
            cp16(sbase + (uint32_t)((buf * BUF + arr * ARR_I + kk * 128 + q * 4) * 4), src);
        }
        {
            const int kk = tid >> 4, q = tid & 15;
            const size_t gk = (size_t)(kb + kk) * NN + J0 + q * 4;
            cp16(sbase + (uint32_t)((buf * BUF + 2 * ARR_I + kk * 64 + q * 4) * 4), g_M1t + gk);
            cp16(sbase + (uint32_t)((buf * BUF + 2 * ARR_I + ARR_J + kk * 64 + q * 4) * 4), g_M2t + gk);
        }
        asm volatile("cp.async.commit_group;\n");
    };

    issue_chunk(0, 0);

    u64 accP[4][4], accQ[4][4];
    #pragma unroll
    for (int r = 0; r < 4; r++)
        #pragma unroll
        for (int c = 0; c < 4; c++) { accP[r][c] = 0ULL; accQ[r][c] = 0ULL; }

    for (int c = 0; c < NCHUNK; c++) {
        const int cur = c & 1;
        if (c < NCHUNK - 1) {
            issue_chunk(c + 1, cur ^ 1);
            asm volatile("cp.async.wait_group 1;\n");
        } else {
            asm volatile("cp.async.wait_group 0;\n");
        }
        __syncthreads();

        const float* M1I = sh + cur * BUF;
        const float* M2I = sh + cur * BUF + ARR_I;
        const float* M1J = sh + cur * BUF + 2 * ARR_I;
        const float* M2J = sh + cur * BUF + 2 * ARR_I + ARR_J;

        #pragma unroll
        for (int kk = 0; kk < BK; kk++) {
            ulonglong2 a1lo = *(const ulonglong2*)&M1I[kk * 128 + ty * 8];
            ulonglong2 a1hi = *(const ulonglong2*)&M1I[kk * 128 + ty * 8 + 4];
            ulonglong2 a2lo = *(const ulonglong2*)&M2I[kk * 128 + ty * 8];
            ulonglong2 a2hi = *(const ulonglong2*)&M2I[kk * 128 + ty * 8 + 4];
            u64 a1p[4] = { a1lo.x, a1lo.y, a1hi.x, a1hi.y };
            u64 a2p[4] = { a2lo.x, a2lo.y, a2hi.x, a2hi.y };
            float4 f1 = *(const float4*)&M1J[kk * 64 + tx * 4];
            float4 f2 = *(const float4*)&M2J[kk * 64 + tx * 4];
            u64 b1d[4] = { pack2(f1.x), pack2(f1.y), pack2(f1.z), pack2(f1.w) };
            u64 b2d[4] = { pack2(f2.x), pack2(f2.y), pack2(f2.z), pack2(f2.w) };
            #pragma unroll
            for (int rp = 0; rp < 4; rp++)
                #pragma unroll
                for (int cc = 0; cc < 4; cc++) {
                    fma2(accP[rp][cc], a1p[rp], b2d[cc]);
                    fma2(accQ[rp][cc], a2p[rp], b1d[cc]);
                }
        }
        __syncthreads();
    }

    float P[8][4], Q[8][4];
    #pragma unroll
    for (int rp = 0; rp < 4; rp++)
        #pragma unroll
        for (int cc = 0; cc < 4; cc++) {
            float2 fp = unpk(accP[rp][cc]);
            float2 fq = unpk(accQ[rp][cc]);
            P[2*rp][cc] = fp.x; P[2*rp+1][cc] = fp.y;
            Q[2*rp][cc] = fq.x; Q[2*rp+1][cc] = fq.y;
        }

    const int ibase = I0 + ty * 8;
    const int jbase = J0 + tx * 4;
    const bool cross = ((bj >> 1) == bi);

    if (!cross) {
        #pragma unroll
        for (int r = 0; r < 8; r++) {
            float4 w;
            w.x = fmaxf(P[r][0] - Q[r][0], 0.0f);
            w.y = fmaxf(P[r][1] - Q[r][1], 0.0f);
            w.z = fmaxf(P[r][2] - Q[r][2], 0.0f);
            w.w = fmaxf(P[r][3] - Q[r][3], 0.0f);
            *(float4*)&aout[(size_t)(ibase + r) * NN + jbase] = w;
        }
        #pragma unroll
        for (int cc = 0; cc < 4; cc++) {
            const int jg = jbase + cc;
            float4 w0, w1;
            w0.x = fmaxf(Q[0][cc] - P[0][cc], 0.0f);
            w0.y = fmaxf(Q[1][cc] - P[1][cc], 0.0f);
            w0.z = fmaxf(Q[2][cc] - P[2][cc], 0.0f);
            w0.w = fmaxf(Q[3][cc] - P[3][cc], 0.0f);
            w1.x = fmaxf(Q[4][cc] - P[4][cc], 0.0f);
            w1.y = fmaxf(Q[5][cc] - P[5][cc], 0.0f);
            w1.z = fmaxf(Q[6][cc] - P[6][cc], 0.0f);
            w1.w = fmaxf(Q[7][cc] - P[7][cc], 0.0f);
            *(float4*)&aout[(size_t)jg * NN + ibase] = w0;
            *(float4*)&aout[(size_t)jg * NN + ibase + 4] = w1;
        }
    } else {
        #pragma unroll
        for (int r = 0; r < 8; r++) {
            const int ig = ibase + r;
            #pragma unroll
            for (int cc = 0; cc < 4; cc++) {
                const int jg = jbase + cc;
                if (jg > ig) {
                    aout[(size_t)ig * NN + jg] = fmaxf(P[r][cc] - Q[r][cc], 0.0f);
                    aout[(size_t)jg * NN + ig] = fmaxf(Q[r][cc] - P[r][cc], 0.0f);
                } else if (jg == ig) {
                    aout[(size_t)ig * NN + jg] = 0.0f;
                }
            }
        }
    }
}

// ============================================================================
// Kernel 3: per-row top-30 via exact threshold selection, smem-resident.
// Keys: (valbits<<13)|(8191-col). T = 30th largest of per-lane top-2 set
// (subset bound: T <= true 30th => candidates contain the true top-30 and
// count >= 30). Candidates <= 64: one warp sort. Else: exact batch-merge of
// all 16 sorted 64-blocks. dyn smem = 69632 B.
// ============================================================================
__device__ __forceinline__ u64 shfl64_xor(u64 x, int off) {
    return __shfl_xor_sync(0xffffffffu, x, off);
}

// warp-collective bitonic sort (descending) of 64 keys, 2/lane, v = 2*lane+r.
// (validated in round 5)
__device__ __forceinline__ void warp_sort64_desc(u64& e0, u64& e1, int lane) {
    #pragma unroll
    for (int size = 2; size <= 64; size <<= 1) {
        #pragma unroll
        for (int stride = size >> 1; stride > 0; stride >>= 1) {
            const bool desc = (((2 * lane) & size) == 0);
            if (stride == 1) {
                const u64 lo = (e0 < e1) ? e0 : e1;
                const u64 hi = (e0 < e1) ? e1 : e0;
                e0 = desc ? hi : lo;
                e1 = desc ? lo : hi;
            } else {
                const int half = stride >> 1;
                const u64 p0 = shfl64_xor(e0, half);
                const u64 p1 = shfl64_xor(e1, half);
                const bool first = (((2 * lane) & stride) == 0);
                const bool keepmax = (first == desc);
                e0 = keepmax ? (e0 > p0 ? e0 : p0) : (e0 < p0 ? e0 : p0);
                e1 = keepmax ? (e1 > p1 ? e1 : p1) : (e1 < p1 ? e1 : p1);
            }
        }
    }
}

// merge two descending sorted 64-lists (t, d), keep top-64 in t (descending).
__device__ __forceinline__ void merge64_desc(u64& t0, u64& t1, u64 d0, u64 d1, int lane) {
    // reversed d: rd[2*lane+0] = d[63-2*lane] = elem (31-lane, r=1); rd[2*lane+1] = (31-lane, r=0)
    const u64 x0 = shfl64_xor(d0, 31);
    const u64 x1 = shfl64_xor(d1, 31);
    u64 e0 = (t0 > x1) ? t0 : x1;
    u64 e1 = (t1 > x0) ? t1 : x0;
    // bitonic merge to descending: element strides 32,16,8,4,2 (lane-xor s), then 1
    #pragma unroll
    for (int s = 16; s >= 1; s >>= 1) {
        const u64 p0 = shfl64_xor(e0, s);
        const u64 p1 = shfl64_xor(e1, s);
        const bool first = ((lane & s) == 0);
        e0 = first ? (e0 > p0 ? e0 : p0) : (e0 < p0 ? e0 : p0);
        e1 = first ? (e1 > p1 ? e1 : p1) : (e1 < p1 ? e1 : p1);
    }
    const u64 hi = (e0 > e1) ? e0 : e1;
    const u64 lo = (e0 > e1) ? e1 : e0;
    t0 = hi; t1 = lo;
}

__global__ void __launch_bounds__(256) topk_kernel(float* __restrict__ out,
                                                   long long abase,
                                                   int write_edges)
{
    extern __shared__ u64 smem_u64[];
    __shared__ u64 wtop[8][TOPK];
    __shared__ u64 topkeys[TOPK];

    const int row = blockIdx.x;
    const int tid = threadIdx.x;
    const int lane = tid & 31;
    const int w = tid >> 5;
    float* arow = out + abase + (size_t)row * NN;

    // per-warp regions: interleaved list [i*32+lane] (conflict-free), 64-slot cand
    u64* list = smem_u64 + w * 1024;
    u64* cand = smem_u64 + 8192 + w * 64;

    // load, zero output row, pack keys -> smem list; track per-lane top-2
    u64 m1 = 0ULL, m2 = 0ULL;
    const float4 z4 = make_float4(0.f, 0.f, 0.f, 0.f);
    #pragma unroll
    for (int q = 0; q < 8; q++) {
        const int base = (tid + 256 * q) * 4;
        float4 t = *(const float4*)&arow[base];
        *(float4*)&arow[base] = z4;
        u64 kk[4];
        kk[0] = ((u64)__float_as_uint(t.x) << 13) | (u64)(8191 - (base + 0));
        kk[1] = ((u64)__float_as_uint(t.y) << 13) | (u64)(8191 - (base + 1));
        kk[2] = ((u64)__float_as_uint(t.z) << 13) | (u64)(8191 - (base + 2));
        kk[3] = ((u64)__float_as_uint(t.w) << 13) | (u64)(8191 - (base + 3));
        #pragma unroll
        for (int c = 0; c < 4; c++) {
            list[(q * 4 + c) * 32 + lane] = kk[c];
            const bool g = kk[c] > m1;
            const u64 nm2 = g ? m1 : ((kk[c] > m2) ? kk[c] : m2);
            m1 = g ? kk[c] : m1;
            m2 = nm2;
        }
    }

    // T = rank-29 (0-based) of the 64 lane-top-2 keys
    warp_sort64_desc(m1, m2, lane);
    const u64 T = __shfl_sync(0xffffffffu, m2, 14);   // v = 2*14+1 = 29

    // zero candidate buffer
    cand[2 * lane] = 0ULL;
    cand[2 * lane + 1] = 0ULL;
    __syncwarp();

    // count + ballot-compact candidates >= T
    int cnt = 0;
    const unsigned lml = (1u << lane) - 1u;
    #pragma unroll
    for (int i = 0; i < 32; i++) {
        const u64 key = list[i * 32 + lane];
        const bool p = (key >= T);
        const unsigned msk = __ballot_sync(0xffffffffu, p);
        if (p) {
            const int pos = cnt + __popc(msk & lml);
            if (pos < 64) cand[pos] = key;
        }
        cnt += __popc(msk);
    }
    __syncwarp();

    u64 t0, t1;
    if (cnt <= 64) {
        // fast path: sort candidates (0-padded), winners = first 30
        t0 = cand[2 * lane];
        t1 = cand[2 * lane + 1];
        warp_sort64_desc(t0, t1, lane);
    } else {
        // exact fallback: batch-merge all 16 sorted 64-blocks of the list
        t0 = list[0 * 32 + lane];
        t1 = list[1 * 32 + lane];
        warp_sort64_desc(t0, t1, lane);
        for (int b = 1; b < 16; b++) {
            u64 d0 = list[(2 * b) * 32 + lane];
            u64 d1 = list[(2 * b + 1) * 32 + lane];
            warp_sort64_desc(d0, d1, lane);
            merge64_desc(t0, t1, d0, d1, lane);
        }
    }
    if (lane < 15) {
        wtop[w][2 * lane] = t0;
        wtop[w][2 * lane + 1] = t1;
    }
    __syncthreads();

    // final merge: warp 0, lanes 0..7 hold sorted 30-list heads
    if (w == 0) {
        int h = 0;
        u64 head = (lane < 8) ? wtop[lane][0] : 0ULL;
        for (int it = 0; it < TOPK; it++) {
            u64 m = head;
            #pragma unroll
            for (int off = 4; off; off >>= 1) {
                const u64 om = shfl64_xor(m, off);
                if (om > m) m = om;
            }
            if (lane == 0) topkeys[it] = m;
            if (lane < 8 && head == m) {
                h++;
                head = (h < TOPK) ? wtop[lane][h] : 0ULL;
            }
        }
    }
    __syncthreads();

    if (tid < TOPK) {
        const u64 key = topkeys[tid];
        const float val = __uint_as_float((unsigned)(key >> 13));
        const int dst = 8191 - (int)(key & 8191);
        arow[dst] = val;
        if (write_edges) {
            const long long e = (long long)row * TOPK + tid;
            out[e] = (float)row;                                // src
            out[(long long)NN * TOPK + e] = (float)dst;         // dst
            out[2LL * NN * TOPK + e] = val;                     // attr
        }
    }
}

// ============================================================================
// launch
// ============================================================================
extern "C" void kernel_launch(void* const* d_in, const int* in_sizes, int n_in,
                              void* d_out, int out_size)
{
    const float* E1 = (const float*)d_in[0];
    const float* E2 = (const float*)d_in[1];
    const float* W1 = (const float*)d_in[2];
    const float* b1 = (const float*)d_in[3];
    const float* W2 = (const float*)d_in[4];
    const float* b2 = (const float*)d_in[5];
    float* out = (float*)d_out;

    cudaFuncSetAttribute(prep_kernel, cudaFuncAttributeMaxDynamicSharedMemorySize, 81920);
    cudaFuncSetAttribute(gemm_kernel, cudaFuncAttributeMaxDynamicSharedMemorySize, 49152);
    cudaFuncSetAttribute(topk_kernel, cudaFuncAttributeMaxDynamicSharedMemorySize, 69632);

    long long abase;
    int write_edges;
    if (out_size == (long long)NN * NN) { abase = 0; write_edges = 0; }
    else { abase = 3LL * NN * TOPK; write_edges = 1; }

    prep_kernel<<<dim3(NN / 32, 2), 256, 81920>>>(E1, W1, b1, E2, W2, b2);
    gemm_kernel<<<dim3(128, 64), 256, 49152>>>(out + abase);
    topk_kernel<<<NN, 256, 69632>>>(out, abase, write_edges);
}